// round 3
// baseline (speedup 1.0000x reference)
#include <cuda_runtime.h>
#include <math.h>
#include <stdint.h>

#define BN   65536      // B*N total nodes
#define NPB  16384      // nodes per batch
#define NE   262144     // total edges (B*E)

// ---------------- device scratch ----------------
__device__ __align__(16) float g_P [(size_t)BN * 128];   // [P1 | P2] per node
__device__ __align__(16) float g_dh[(size_t)BN * 64];    // scattered m_ij
__device__ __align__(16) float g_dx[(size_t)BN * 3];     // scattered delta_x
__device__ __align__(16) float g_t [(size_t)BN * 128];   // silu(h_input @ ph_w1 + b1)

__device__ __forceinline__ float silu_f(float v) {
    return v * (1.0f / (1.0f + __expf(-v)));
}

__device__ __forceinline__ uint32_t f2tf32(float f) {
    uint32_t r;
    asm("cvt.rna.tf32.f32 %0, %1;" : "=r"(r) : "f"(f));
    return r;
}

__device__ __forceinline__ void mma_tf32(float* c, const uint32_t* a, const uint32_t* b) {
    asm volatile("mma.sync.aligned.m16n8k8.row.col.f32.tf32.tf32.f32 "
        "{%0,%1,%2,%3}, {%4,%5,%6,%7}, {%8,%9}, {%0,%1,%2,%3};"
        : "+f"(c[0]), "+f"(c[1]), "+f"(c[2]), "+f"(c[3])
        : "r"(a[0]), "r"(a[1]), "r"(a[2]), "r"(a[3]), "r"(b[0]), "r"(b[1]));
}

__device__ __forceinline__ void red_add_v4(float* p, float4 v) {
    asm volatile("red.global.add.v4.f32 [%0], {%1,%2,%3,%4};"
                 :: "l"(p), "f"(v.x), "f"(v.y), "f"(v.z), "f"(v.w) : "memory");
}

// ---------------- zero the scatter accumulators ----------------
__global__ void zero_kernel() {
    float4 z = make_float4(0.f, 0.f, 0.f, 0.f);
    const size_t n1 = (size_t)BN * 16;       // g_dh in float4
    const size_t n2 = (size_t)BN * 3 / 4;    // g_dx in float4
    const size_t total = n1 + n2;
    for (size_t i = (size_t)blockIdx.x * blockDim.x + threadIdx.x; i < total;
         i += (size_t)gridDim.x * blockDim.x) {
        if (i < n1) ((float4*)g_dh)[i] = z;
        else        ((float4*)g_dx)[i - n1] = z;
    }
}

// ================== tf32 TC GEMM: CTA tile 256x128, warp tile 64x64 =========
// MODE 0: C=g_P : A=h (K=128),        B=pe_w1 split [W1a|W1b], no bias
// MODE 1: C=g_t : A=[h|g_dh] (K=192), B=ph_w1, bias=ph_b1, silu
// MODE 2: C=out : A=g_t (K=128),      B=ph_w2, bias=ph_b2, +h residual (A = h)
// smem: per buffer  sA[256][40] (k-pair interleaved), sB[128][40] (transposed,
// k-pair interleaved).  slot(kk) = (kk&3)*2 + (kk>>2)  => (k, k+4) adjacent.
template<int MODE, int KTOT>
__global__ __launch_bounds__(256, 1) void gemm_tc(
    const float* __restrict__ A,
    const float* __restrict__ Bm,
    const float* __restrict__ bias,
    float* __restrict__ Cout)
{
    extern __shared__ uint32_t sm[];
    const int SA = 256 * 40;
    const int SB = 128 * 40;
    const int BUFW = SA + SB;

    const int tid  = threadIdx.x;
    const int lane = tid & 31, warp = tid >> 5;
    const int wm = warp & 3, wn = warp >> 2;          // 4 warps M x 2 warps N
    const int gq = lane >> 2, tq = lane & 3;
    const int m0 = blockIdx.x * 256;
    const int NC = KTOT / 32;

    float acc[4][8][4];
#pragma unroll
    for (int i = 0; i < 4; i++)
#pragma unroll
        for (int j = 0; j < 8; j++)
#pragma unroll
            for (int q = 0; q < 4; q++) acc[i][j][q] = 0.f;

    float4 ra[4][2];
    float4 rb[4];

    // ---- global loads for chunk k0 into regs ----
    auto ldg_chunk = [&](int k0) {
#pragma unroll
        for (int it = 0; it < 4; it++) {
            const int task = it * 256 + tid;
            const int m = task >> 2, g = task & 3;
            const int f = k0 + g * 8;
            const float* src;
            if (MODE == 1) {
                src = (f < 128) ? (A + (size_t)(m0 + m) * 128 + f)
                                : (g_dh + (size_t)(m0 + m) * 64 + (f - 128));
            } else if (MODE == 2) {
                src = g_t + (size_t)(m0 + m) * 128 + f;
            } else {
                src = A + (size_t)(m0 + m) * 128 + f;
            }
            ra[it][0] = *(const float4*)(src);
            ra[it][1] = *(const float4*)(src + 4);
        }
#pragma unroll
        for (int it = 0; it < 4; it++) {
            const int k  = tid & 31;
            const int n4 = (tid >> 5) + it * 8;
            const float* src;
            if (MODE == 0) {
                src = (n4 < 16) ? (Bm + (size_t)(k0 + k) * 64 + n4 * 4)
                                : (Bm + (size_t)(128 + k0 + k) * 64 + (n4 - 16) * 4);
            } else {
                src = Bm + (size_t)(k0 + k) * 128 + n4 * 4;
            }
            rb[it] = *(const float4*)src;
        }
    };

    // ---- store regs -> smem buffer p (tf32 convert + k-pair interleave) ----
    auto sts_chunk = [&](int p) {
        uint32_t* bA = sm + p * BUFW;
        uint32_t* bB = sm + p * BUFW + SA;
#pragma unroll
        for (int it = 0; it < 4; it++) {
            const int task = it * 256 + tid;
            const int m = task >> 2, g = task & 3;
            const float4 u = ra[it][0], v = ra[it][1];
            uint4 w0, w1;
            w0.x = f2tf32(u.x); w0.y = f2tf32(v.x); w0.z = f2tf32(u.y); w0.w = f2tf32(v.y);
            w1.x = f2tf32(u.z); w1.y = f2tf32(v.z); w1.z = f2tf32(u.w); w1.w = f2tf32(v.w);
            *(uint4*)&bA[m * 40 + g * 8]     = w0;
            *(uint4*)&bA[m * 40 + g * 8 + 4] = w1;
        }
#pragma unroll
        for (int it = 0; it < 4; it++) {
            const int k  = tid & 31;
            const int n4 = (tid >> 5) + it * 8;
            const int g = k >> 3, kk = k & 7;
            const int slot = (kk & 3) * 2 + (kk >> 2);
            const float4 b = rb[it];
            bB[(n4 * 4 + 0) * 40 + g * 8 + slot] = f2tf32(b.x);
            bB[(n4 * 4 + 1) * 40 + g * 8 + slot] = f2tf32(b.y);
            bB[(n4 * 4 + 2) * 40 + g * 8 + slot] = f2tf32(b.z);
            bB[(n4 * 4 + 3) * 40 + g * 8 + slot] = f2tf32(b.w);
        }
    };

    auto compute = [&](int p) {
        const uint32_t* bA = sm + p * BUFW;
        const uint32_t* bB = sm + p * BUFW + SA;
#pragma unroll
        for (int ks = 0; ks < 4; ks++) {
            uint32_t af[4][4], bf[8][2];
#pragma unroll
            for (int i = 0; i < 4; i++) {
                const int r = wm * 64 + i * 16 + gq;
                const uint2 lo = *(const uint2*)&bA[r * 40 + ks * 8 + 2 * tq];
                const uint2 hi = *(const uint2*)&bA[(r + 8) * 40 + ks * 8 + 2 * tq];
                af[i][0] = lo.x; af[i][1] = hi.x; af[i][2] = lo.y; af[i][3] = hi.y;
            }
#pragma unroll
            for (int j = 0; j < 8; j++) {
                const int c = wn * 64 + j * 8 + gq;
                const uint2 b = *(const uint2*)&bB[c * 40 + ks * 8 + 2 * tq];
                bf[j][0] = b.x; bf[j][1] = b.y;
            }
#pragma unroll
            for (int i = 0; i < 4; i++)
#pragma unroll
                for (int j = 0; j < 8; j++)
                    mma_tf32(acc[i][j], af[i], bf[j]);
        }
    };

    ldg_chunk(0);
    sts_chunk(0);
    __syncthreads();
    for (int c = 0; c < NC; c++) {
        if (c + 1 < NC) ldg_chunk((c + 1) * 32);
        compute(c & 1);
        if (c + 1 < NC) sts_chunk((c + 1) & 1);
        __syncthreads();
    }

    // ---- epilogue ----
#pragma unroll
    for (int i = 0; i < 4; i++) {
#pragma unroll
        for (int h2 = 0; h2 < 2; h2++) {
            const int r = m0 + wm * 64 + i * 16 + gq + h2 * 8;
#pragma unroll
            for (int j = 0; j < 8; j++) {
                const int c = wn * 64 + j * 8 + tq * 2;
                float v0 = acc[i][j][h2 * 2 + 0];
                float v1 = acc[i][j][h2 * 2 + 1];
                const size_t base = (size_t)r * 128 + c;
                if (MODE == 0) {
                    *(float2*)(g_P + base) = make_float2(v0, v1);
                } else if (MODE == 1) {
                    v0 = silu_f(v0 + __ldg(bias + c));
                    v1 = silu_f(v1 + __ldg(bias + c + 1));
                    *(float2*)(g_t + base) = make_float2(v0, v1);
                } else {
                    const float2 hh = *(const float2*)(A + base);
                    v0 += __ldg(bias + c) + hh.x;
                    v1 += __ldg(bias + c + 1) + hh.y;
                    *(float2*)(Cout + base) = make_float2(v0, v1);
                }
            }
        }
    }
}

// ---------------- edge kernel: 128 edges/block, 256 threads, tf32 GEMM2 ----
__global__ __launch_bounds__(256) void edge_kernel(
    const float* __restrict__ x,
    const int*   __restrict__ edges,
    const float* __restrict__ W1,
    const float* __restrict__ b1,
    const float* __restrict__ W2,
    const float* __restrict__ b2,
    const float* __restrict__ pxw)
{
    extern __shared__ uint32_t dyn[];
    uint32_t* sW2 = dyn;                 // [64][68] tf32
    uint32_t* sM  = dyn + 64 * 68;       // [128][68] tf32 (silu(m))
    float*    sOut = (float*)(dyn + 64 * 68);   // reuse sM region after GEMM2

    __shared__ int   sSrc[128], sDst[128];
    __shared__ float sD2[128];
    __shared__ float sDirx[128], sDiry[128], sDirz[128];
    __shared__ float sB1[64], sB2[64], sPx[64], sW1r[64];

    const int tid  = threadIdx.x;
    const int lane = tid & 31, warp = tid >> 5;
    const int gq = lane >> 2, tq = lane & 3;
    const int e0 = blockIdx.x * 128;

    if (tid < 128) {
        const int eg = e0 + tid;
        const int b  = eg >> 16;                 // E per batch = 65536
        const int2 sd = ((const int2*)edges)[eg];
        const int gi = b * NPB + sd.x;
        const int gj = b * NPB + sd.y;
        sSrc[tid] = gi; sDst[tid] = gj;
        const float xi0 = x[(size_t)gi * 3 + 0], xi1 = x[(size_t)gi * 3 + 1], xi2 = x[(size_t)gi * 3 + 2];
        const float xj0 = x[(size_t)gj * 3 + 0], xj1 = x[(size_t)gj * 3 + 1], xj2 = x[(size_t)gj * 3 + 2];
        const float d0 = xi0 - xj0, d1 = xi1 - xj1, d2c = xi2 - xj2;
        float d2 = d0 * d0 + d1 * d1 + d2c * d2c;
        d2 = fmaxf(d2, 1e-12f);
        sD2[tid] = d2;
        const float inv = 1.0f / (sqrtf(d2) + 1e-8f);
        sDirx[tid] = d0 * inv; sDiry[tid] = d1 * inv; sDirz[tid] = d2c * inv;
    }
    if (tid < 64) {
        sB1[tid] = b1[tid];
        sB2[tid] = b2[tid];
        sPx[tid] = pxw[tid];
        sW1r[tid] = W1[256 * 64 + tid];
    }
#pragma unroll
    for (int i = 0; i < 4; i++) {
        const int lin = i * 256 + tid;
        const int k = lin >> 4, nq = lin & 15;
        const float4 v = *(const float4*)(W2 + (size_t)k * 64 + nq * 4);
        uint32_t* d = sW2 + k * 68 + nq * 4;
        d[0] = f2tf32(v.x); d[1] = f2tf32(v.y);
        d[2] = f2tf32(v.z); d[3] = f2tf32(v.w);
    }
    __syncthreads();

    // m tile: silu(P1[src] + P2[dst] + dist2*W1r + b1) -> tf32 smem [e][68]
#pragma unroll 4
    for (int it = 0; it < 32; ++it) {
        const int idx = it * 256 + tid;
        const int e = idx >> 6, k = idx & 63;
        float v = g_P[(size_t)sSrc[e] * 128 + k]
                + g_P[(size_t)sDst[e] * 128 + 64 + k]
                + sD2[e] * sW1r[k] + sB1[k];
        sM[e * 68 + k] = f2tf32(silu_f(v));
    }
    __syncthreads();

    // GEMM2 via tf32 mma: each warp handles 16 edges x 64 cols
    float acc[8][4];
#pragma unroll
    for (int j = 0; j < 8; j++)
#pragma unroll
        for (int q = 0; q < 4; q++) acc[j][q] = 0.f;

#pragma unroll
    for (int ks = 0; ks < 8; ks++) {
        const int kb = ks * 8;
        uint32_t af[4], bf[2];
        const int r = warp * 16 + gq;
        af[0] = sM[r * 68 + kb + tq];           af[1] = sM[(r + 8) * 68 + kb + tq];
        af[2] = sM[r * 68 + kb + tq + 4];       af[3] = sM[(r + 8) * 68 + kb + tq + 4];
#pragma unroll
        for (int j = 0; j < 8; j++) {
            const int c = j * 8 + gq;
            bf[0] = sW2[(kb + tq) * 68 + c];
            bf[1] = sW2[(kb + tq + 4) * 68 + c];
            mma_tf32(acc[j], af, bf);
        }
    }
    __syncthreads();   // all warps done reading sM/sW2 — safe to overlay sOut

    // epilogue: silu(+b2) -> sOut; m_x dot + scatter delta_x
    const int r0 = warp * 16 + gq;
    float part0 = 0.f, part1 = 0.f;
#pragma unroll
    for (int j = 0; j < 8; j++) {
        const int c = j * 8 + tq * 2;
        const float bb0 = sB2[c], bb1 = sB2[c + 1];
        const float px0 = sPx[c], px1 = sPx[c + 1];
        {
            const float v0 = silu_f(acc[j][0] + bb0);
            const float v1 = silu_f(acc[j][1] + bb1);
            *(float2*)&sOut[r0 * 68 + c] = make_float2(v0, v1);
            part0 += v0 * px0 + v1 * px1;
        }
        {
            const float v0 = silu_f(acc[j][2] + bb0);
            const float v1 = silu_f(acc[j][3] + bb1);
            *(float2*)&sOut[(r0 + 8) * 68 + c] = make_float2(v0, v1);
            part1 += v0 * px0 + v1 * px1;
        }
    }
    part0 += __shfl_xor_sync(0xffffffffu, part0, 1);
    part0 += __shfl_xor_sync(0xffffffffu, part0, 2);
    part1 += __shfl_xor_sync(0xffffffffu, part1, 1);
    part1 += __shfl_xor_sync(0xffffffffu, part1, 2);
    if (tq == 0) {
        const int n0 = sSrc[r0], n1 = sSrc[r0 + 8];
        atomicAdd(&g_dx[(size_t)n0 * 3 + 0], part0 * sDirx[r0]);
        atomicAdd(&g_dx[(size_t)n0 * 3 + 1], part0 * sDiry[r0]);
        atomicAdd(&g_dx[(size_t)n0 * 3 + 2], part0 * sDirz[r0]);
        atomicAdd(&g_dx[(size_t)n1 * 3 + 0], part1 * sDirx[r0 + 8]);
        atomicAdd(&g_dx[(size_t)n1 * 3 + 1], part1 * sDiry[r0 + 8]);
        atomicAdd(&g_dx[(size_t)n1 * 3 + 2], part1 * sDirz[r0 + 8]);
    }
    __syncthreads();

    // scatter m2 -> g_dh with vector reductions (2 threads per edge)
    {
        const int e    = tid & 127;
        const int half = tid >> 7;
        const int node = sSrc[e];
        float* dst = g_dh + (size_t)node * 64 + half * 32;
        const float* src = sOut + e * 68 + half * 32;
#pragma unroll
        for (int i = 0; i < 8; i++) {
            const float4 v = *(const float4*)(src + i * 4);
            red_add_v4(dst + i * 4, v);
        }
    }
}

// ---------------- x_new = x + delta_x ----------------
__global__ void xout_kernel(const float* __restrict__ x, float* __restrict__ out) {
    const int i = blockIdx.x * blockDim.x + threadIdx.x;
    if (i < BN * 3) out[i] = x[i] + g_dx[i];
}

// ---------------- launch ----------------
extern "C" void kernel_launch(void* const* d_in, const int* in_sizes, int n_in,
                              void* d_out, int out_size) {
    const float* x   = (const float*)d_in[0];
    const float* h   = (const float*)d_in[1];
    const int*   ei  = (const int*)d_in[2];
    const float* pw1 = (const float*)d_in[3];
    const float* pb1 = (const float*)d_in[4];
    const float* pw2 = (const float*)d_in[5];
    const float* pb2 = (const float*)d_in[6];
    const float* pxw = (const float*)d_in[7];
    const float* hw1 = (const float*)d_in[8];
    const float* hb1 = (const float*)d_in[9];
    const float* hw2 = (const float*)d_in[10];
    const float* hb2 = (const float*)d_in[11];

    float* out   = (float*)d_out;
    float* out_x = out;                      // (B,N,3) first
    float* out_h = out + (size_t)BN * 3;     // then (B,N,128)

    const int GSMEM = 2 * (256 * 40 + 128 * 40) * (int)sizeof(uint32_t);  // 122880 B
    const int EDGE_SMEM = (64 * 68 + 128 * 68) * (int)sizeof(uint32_t);   // 52224 B
    cudaFuncSetAttribute(gemm_tc<0, 128>, cudaFuncAttributeMaxDynamicSharedMemorySize, GSMEM);
    cudaFuncSetAttribute(gemm_tc<1, 192>, cudaFuncAttributeMaxDynamicSharedMemorySize, GSMEM);
    cudaFuncSetAttribute(gemm_tc<2, 128>, cudaFuncAttributeMaxDynamicSharedMemorySize, GSMEM);
    cudaFuncSetAttribute(edge_kernel, cudaFuncAttributeMaxDynamicSharedMemorySize, EDGE_SMEM);

    zero_kernel<<<1024, 256>>>();
    gemm_tc<0, 128><<<BN / 256, 256, GSMEM>>>(h, pw1, nullptr, nullptr);       // g_P
    edge_kernel<<<NE / 128, 256, EDGE_SMEM>>>(x, ei, pw1, pb1, pw2, pb2, pxw); // g_dh, g_dx
    gemm_tc<1, 192><<<BN / 256, 256, GSMEM>>>(h, hw1, hb1, nullptr);           // g_t
    gemm_tc<2, 128><<<BN / 256, 256, GSMEM>>>(h, hw2, hb2, out_h);             // h_new
    xout_kernel<<<(BN * 3 + 255) / 256, 256>>>(x, out_x);                      // x_new
}

// round 4
// speedup vs baseline: 1.0100x; 1.0100x over previous
#include <cuda_runtime.h>
#include <math.h>
#include <stdint.h>

#define BN   65536      // B*N total nodes
#define NPB  16384      // nodes per batch
#define NE   262144     // total edges (B*E)

// ---------------- device scratch ----------------
__device__ __align__(16) float g_P [(size_t)BN * 128];   // [P1 | P2] per node
__device__ __align__(16) float g_dh[(size_t)BN * 64];    // scattered m_ij
__device__ __align__(16) float g_dx[(size_t)BN * 3];     // scattered delta_x
__device__ __align__(16) float g_t [(size_t)BN * 128];   // silu(h_input @ ph_w1 + b1)
// Prepped weights: 14 K-chunks x 128 n-rows x 40 words (tf32, k-pair interleaved)
// chunks 0-3: mode0 (pe_w1 split), 4-9: mode1 (ph_w1), 10-13: mode2 (ph_w2)
__device__ __align__(16) float g_Bp[14 * 128 * 40];
__device__ __align__(16) float g_W2p[64 * 72];            // pe_w2, [n][72] interleaved

__device__ __forceinline__ float silu_f(float v) {
    return v * (1.0f / (1.0f + __expf(-v)));
}

__device__ __forceinline__ uint32_t f2tf32(float f) {
    uint32_t r;
    asm("cvt.rna.tf32.f32 %0, %1;" : "=r"(r) : "f"(f));
    return r;
}

__device__ __forceinline__ void mma_tf32(float* c, const uint32_t* a, const uint32_t* b) {
    asm volatile("mma.sync.aligned.m16n8k8.row.col.f32.tf32.tf32.f32 "
        "{%0,%1,%2,%3}, {%4,%5,%6,%7}, {%8,%9}, {%0,%1,%2,%3};"
        : "+f"(c[0]), "+f"(c[1]), "+f"(c[2]), "+f"(c[3])
        : "r"(a[0]), "r"(a[1]), "r"(a[2]), "r"(a[3]), "r"(b[0]), "r"(b[1]));
}

__device__ __forceinline__ void red_add_v4(float* p, float4 v) {
    asm volatile("red.global.add.v4.f32 [%0], {%1,%2,%3,%4};"
                 :: "l"(p), "f"(v.x), "f"(v.y), "f"(v.z), "f"(v.w) : "memory");
}

__device__ __forceinline__ void cp_async16(uint32_t dst, const void* src) {
    asm volatile("cp.async.cg.shared.global [%0], [%1], 16;" :: "r"(dst), "l"(src));
}

// slot within an 8-k group: k and k+4 adjacent -> LDS.64 fragment loads
__device__ __forceinline__ int kslot(int kk) { return ((kk & 3) << 1) + (kk >> 2); }

// ---------------- weight prep: reshuffle + tf32-convert once ----------------
__global__ void prep_kernel(const float* __restrict__ pw1,
                            const float* __restrict__ hw1,
                            const float* __restrict__ hw2,
                            const float* __restrict__ pw2)
{
    const int stride = gridDim.x * blockDim.x;
    const int idx0 = blockIdx.x * blockDim.x + threadIdx.x;
    // g_Bp: 14 chunks x 128 n x 40 words
    for (int i = idx0; i < 14 * 128 * 40; i += stride) {
        const int w = i % 40, n = (i / 40) & 127, c = i / (40 * 128);
        float v = 0.f;
        if (w < 32) {
            const int g = w >> 3, s = w & 7;
            const int k8 = (s >> 1) + ((s & 1) << 2);
            if (c < 4) {                 // pe_w1 split [W1a|W1b]
                const int k = c * 32 + g * 8 + k8;
                v = (n < 64) ? pw1[k * 64 + n] : pw1[(128 + k) * 64 + (n - 64)];
            } else if (c < 10) {         // ph_w1, K=192
                const int k = (c - 4) * 32 + g * 8 + k8;
                v = hw1[k * 128 + n];
            } else {                     // ph_w2, K=128
                const int k = (c - 10) * 32 + g * 8 + k8;
                v = hw2[k * 128 + n];
            }
            v = __uint_as_float(f2tf32(v));
        }
        g_Bp[i] = v;
    }
    // g_W2p: 64 n x 72 words (K=64)
    for (int i = idx0; i < 64 * 72; i += stride) {
        const int w = i % 72, n = i / 72;
        float v = 0.f;
        if (w < 64) {
            const int g = w >> 3, s = w & 7;
            const int k = g * 8 + (s >> 1) + ((s & 1) << 2);
            v = __uint_as_float(f2tf32(pw2[k * 64 + n]));
        }
        g_W2p[i] = v;
    }
}

// ---------------- zero the scatter accumulators ----------------
__global__ void zero_kernel() {
    float4 z = make_float4(0.f, 0.f, 0.f, 0.f);
    const size_t n1 = (size_t)BN * 16;       // g_dh in float4
    const size_t n2 = (size_t)BN * 3 / 4;    // g_dx in float4
    const size_t total = n1 + n2;
    for (size_t i = (size_t)blockIdx.x * blockDim.x + threadIdx.x; i < total;
         i += (size_t)gridDim.x * blockDim.x) {
        if (i < n1) ((float4*)g_dh)[i] = z;
        else        ((float4*)g_dx)[i - n1] = z;
    }
}

// ============ tf32 TC GEMM: CTA 128x128, warp 32x64, double-buffered ========
// MODE 0: C=g_P : A=h (K=128)
// MODE 1: C=g_t : A=[h|g_dh] (K=192), bias+silu
// MODE 2: C=out : A=g_t (K=128), bias + h residual (A param = h)
// smem/buf: bA[128][40] interleaved, bB[128][40] (n-major, interleaved) = 40960B
template<int MODE, int KTOT, int BOFF>
__global__ __launch_bounds__(256, 2) void gemm_tc(
    const float* __restrict__ A,
    const float* __restrict__ bias,
    float* __restrict__ Cout)
{
    extern __shared__ float sm[];
    const int BUFW = 10240;                   // words per buffer (A 5120 + B 5120)

    const int tid  = threadIdx.x;
    const int lane = tid & 31, warp = tid >> 5;
    const int wm = warp & 3, wn = warp >> 2;  // 4 warps M x 2 warps N
    const int gq = lane >> 2, tq = lane & 3;
    const int m0 = blockIdx.x * 128;
    const int NC = KTOT / 32;

    const uint32_t smem_u32 = (uint32_t)__cvta_generic_to_shared(sm);

    float acc[2][8][4];
#pragma unroll
    for (int i = 0; i < 2; i++)
#pragma unroll
        for (int j = 0; j < 8; j++)
#pragma unroll
            for (int q = 0; q < 4; q++) acc[i][j][q] = 0.f;

    float4 ra[4];
    const int am = tid >> 1;                  // A row (0..127)
    const int ah = (tid & 1) * 16;            // k offset within chunk (0 or 16)

    auto ldgA = [&](int k0) {
        const int f = k0 + ah;
        const float* src;
        if (MODE == 1) {
            src = (f < 128) ? (A + (size_t)(m0 + am) * 128 + f)
                            : (g_dh + (size_t)(m0 + am) * 64 + (f - 128));
        } else if (MODE == 2) {
            src = g_t + (size_t)(m0 + am) * 128 + f;
        } else {
            src = A + (size_t)(m0 + am) * 128 + f;
        }
        ra[0] = *(const float4*)(src);
        ra[1] = *(const float4*)(src + 4);
        ra[2] = *(const float4*)(src + 8);
        ra[3] = *(const float4*)(src + 12);
    };

    auto stsA = [&](int p) {
        float* bA = sm + p * BUFW;
#pragma unroll
        for (int pg = 0; pg < 2; pg++) {
            const float4 u = ra[pg * 2], v = ra[pg * 2 + 1];
            uint4 w0, w1;
            w0.x = f2tf32(u.x); w0.y = f2tf32(v.x); w0.z = f2tf32(u.y); w0.w = f2tf32(v.y);
            w1.x = f2tf32(u.z); w1.y = f2tf32(v.z); w1.z = f2tf32(u.w); w1.w = f2tf32(v.w);
            *(uint4*)&bA[am * 40 + ah + pg * 8]     = w0;
            *(uint4*)&bA[am * 40 + ah + pg * 8 + 4] = w1;
        }
    };

    auto cpB = [&](int c, int p) {
        const float* src = g_Bp + (size_t)(BOFF + c) * 5120;
        const uint32_t dst = smem_u32 + (p * BUFW + 5120) * 4;
#pragma unroll
        for (int it = 0; it < 5; it++) {
            const int q = tid + it * 256;     // uint4 index < 1280
            cp_async16(dst + q * 16, src + q * 4);
        }
        asm volatile("cp.async.commit_group;" ::: "memory");
    };

    auto compute = [&](int p) {
        const uint32_t* bA = (const uint32_t*)(sm + p * BUFW);
        const uint32_t* bB = (const uint32_t*)(sm + p * BUFW + 5120);
#pragma unroll
        for (int ks = 0; ks < 4; ks++) {
            uint32_t af[2][4], bf[8][2];
#pragma unroll
            for (int i = 0; i < 2; i++) {
                const int r = wm * 32 + i * 16 + gq;
                const uint2 lo = *(const uint2*)&bA[r * 40 + ks * 8 + 2 * tq];
                const uint2 hi = *(const uint2*)&bA[(r + 8) * 40 + ks * 8 + 2 * tq];
                af[i][0] = lo.x; af[i][1] = hi.x; af[i][2] = lo.y; af[i][3] = hi.y;
            }
#pragma unroll
            for (int j = 0; j < 8; j++) {
                const int c = wn * 64 + j * 8 + gq;
                const uint2 b = *(const uint2*)&bB[c * 40 + ks * 8 + 2 * tq];
                bf[j][0] = b.x; bf[j][1] = b.y;
            }
#pragma unroll
            for (int i = 0; i < 2; i++)
#pragma unroll
                for (int j = 0; j < 8; j++)
                    mma_tf32(acc[i][j], af[i], bf[j]);
        }
    };

    ldgA(0);
    cpB(0, 0);
    stsA(0);
    asm volatile("cp.async.wait_group 0;" ::: "memory");
    __syncthreads();
    for (int c = 0; c < NC; c++) {
        if (c + 1 < NC) { ldgA((c + 1) * 32); cpB(c + 1, (c + 1) & 1); }
        compute(c & 1);
        if (c + 1 < NC) stsA((c + 1) & 1);
        asm volatile("cp.async.wait_group 0;" ::: "memory");
        __syncthreads();
    }

    // ---- epilogue ----
#pragma unroll
    for (int i = 0; i < 2; i++) {
#pragma unroll
        for (int h2 = 0; h2 < 2; h2++) {
            const int r = m0 + wm * 32 + i * 16 + gq + h2 * 8;
#pragma unroll
            for (int j = 0; j < 8; j++) {
                const int c = wn * 64 + j * 8 + tq * 2;
                float v0 = acc[i][j][h2 * 2 + 0];
                float v1 = acc[i][j][h2 * 2 + 1];
                const size_t base = (size_t)r * 128 + c;
                if (MODE == 0) {
                    *(float2*)(g_P + base) = make_float2(v0, v1);
                } else if (MODE == 1) {
                    v0 = silu_f(v0 + __ldg(bias + c));
                    v1 = silu_f(v1 + __ldg(bias + c + 1));
                    *(float2*)(g_t + base) = make_float2(v0, v1);
                } else {
                    const float2 hh = *(const float2*)(A + base);
                    v0 += __ldg(bias + c) + hh.x;
                    v1 += __ldg(bias + c + 1) + hh.y;
                    *(float2*)(Cout + base) = make_float2(v0, v1);
                }
            }
        }
    }
}

// ---------------- edge kernel: 128 edges/block, 256 threads ----------------
__global__ __launch_bounds__(256) void edge_kernel(
    const float* __restrict__ x,
    const int*   __restrict__ edges,
    const float* __restrict__ W1,
    const float* __restrict__ b1,
    const float* __restrict__ b2,
    const float* __restrict__ pxw)
{
    extern __shared__ float dyn[];
    float* sW2 = dyn;                    // [64][72] tf32, interleaved
    float* sM  = dyn + 64 * 72;          // [128][72] tf32, interleaved
    float* sOut = sM;                    // overlay after GEMM2
    const uint32_t* sW2u = (const uint32_t*)sW2;
    const uint32_t* sMu  = (const uint32_t*)sM;

    __shared__ int   sSrc[128], sDst[128];
    __shared__ float sD2[128];
    __shared__ float sDirx[128], sDiry[128], sDirz[128];
    __shared__ float sB1[64], sB2[64], sPx[64], sW1r[64];

    const int tid  = threadIdx.x;
    const int lane = tid & 31, warp = tid >> 5;
    const int gq = lane >> 2, tq = lane & 3;
    const int e0 = blockIdx.x * 128;

    if (tid < 128) {
        const int eg = e0 + tid;
        const int b  = eg >> 16;                 // E per batch = 65536
        const int2 sd = ((const int2*)edges)[eg];
        const int gi = b * NPB + sd.x;
        const int gj = b * NPB + sd.y;
        sSrc[tid] = gi; sDst[tid] = gj;
        const float xi0 = x[(size_t)gi * 3 + 0], xi1 = x[(size_t)gi * 3 + 1], xi2 = x[(size_t)gi * 3 + 2];
        const float xj0 = x[(size_t)gj * 3 + 0], xj1 = x[(size_t)gj * 3 + 1], xj2 = x[(size_t)gj * 3 + 2];
        const float d0 = xi0 - xj0, d1 = xi1 - xj1, d2c = xi2 - xj2;
        float d2 = d0 * d0 + d1 * d1 + d2c * d2c;
        d2 = fmaxf(d2, 1e-12f);
        sD2[tid] = d2;
        const float inv = 1.0f / (sqrtf(d2) + 1e-8f);
        sDirx[tid] = d0 * inv; sDiry[tid] = d1 * inv; sDirz[tid] = d2c * inv;
    }
    if (tid < 64) {
        sB1[tid] = b1[tid];
        sB2[tid] = b2[tid];
        sPx[tid] = pxw[tid];
        sW1r[tid] = W1[256 * 64 + tid];
    }
    // W2 prepped: straight copy 64*72 words = 1152 uint4
#pragma unroll
    for (int it = 0; it < 5; it++) {
        const int q = tid + it * 256;
        if (q < 1152) *(float4*)&sW2[q * 4] = *(const float4*)&g_W2p[q * 4];
    }
    __syncthreads();

    // m tile: silu(P1[src] + P2[dst] + dist2*W1r + b1) -> interleaved tf32
#pragma unroll 4
    for (int it = 0; it < 32; ++it) {
        const int idx = it * 256 + tid;
        const int e = idx >> 6, k = idx & 63;
        float v = g_P[(size_t)sSrc[e] * 128 + k]
                + g_P[(size_t)sDst[e] * 128 + 64 + k]
                + sD2[e] * sW1r[k] + sB1[k];
        sM[e * 72 + (k >> 3) * 8 + kslot(k & 7)] = __uint_as_float(f2tf32(silu_f(v)));
    }
    __syncthreads();

    // GEMM2 via tf32 mma: each warp 16 edges x 64 cols, K=64
    float acc[8][4];
#pragma unroll
    for (int j = 0; j < 8; j++)
#pragma unroll
        for (int q = 0; q < 4; q++) acc[j][q] = 0.f;

#pragma unroll
    for (int ks = 0; ks < 8; ks++) {
        uint32_t af[4], bf[2];
        const int r = warp * 16 + gq;
        const uint2 lo = *(const uint2*)&sMu[r * 72 + ks * 8 + 2 * tq];
        const uint2 hi = *(const uint2*)&sMu[(r + 8) * 72 + ks * 8 + 2 * tq];
        af[0] = lo.x; af[1] = hi.x; af[2] = lo.y; af[3] = hi.y;
#pragma unroll
        for (int j = 0; j < 8; j++) {
            const int c = j * 8 + gq;
            const uint2 b = *(const uint2*)&sW2u[c * 72 + ks * 8 + 2 * tq];
            bf[0] = b.x; bf[1] = b.y;
            mma_tf32(acc[j], af, bf);
        }
    }
    __syncthreads();   // done reading sM/sW2 -> safe to overlay sOut

    // epilogue: silu(+b2) -> sOut; m_x dot + scatter delta_x
    const int r0 = warp * 16 + gq;
    float part0 = 0.f, part1 = 0.f;
#pragma unroll
    for (int j = 0; j < 8; j++) {
        const int c = j * 8 + tq * 2;
        const float bb0 = sB2[c], bb1 = sB2[c + 1];
        const float px0 = sPx[c], px1 = sPx[c + 1];
        {
            const float v0 = silu_f(acc[j][0] + bb0);
            const float v1 = silu_f(acc[j][1] + bb1);
            *(float2*)&sOut[r0 * 72 + c] = make_float2(v0, v1);
            part0 += v0 * px0 + v1 * px1;
        }
        {
            const float v0 = silu_f(acc[j][2] + bb0);
            const float v1 = silu_f(acc[j][3] + bb1);
            *(float2*)&sOut[(r0 + 8) * 72 + c] = make_float2(v0, v1);
            part1 += v0 * px0 + v1 * px1;
        }
    }
    part0 += __shfl_xor_sync(0xffffffffu, part0, 1);
    part0 += __shfl_xor_sync(0xffffffffu, part0, 2);
    part1 += __shfl_xor_sync(0xffffffffu, part1, 1);
    part1 += __shfl_xor_sync(0xffffffffu, part1, 2);
    if (tq == 0) {
        const int n0 = sSrc[r0], n1 = sSrc[r0 + 8];
        atomicAdd(&g_dx[(size_t)n0 * 3 + 0], part0 * sDirx[r0]);
        atomicAdd(&g_dx[(size_t)n0 * 3 + 1], part0 * sDiry[r0]);
        atomicAdd(&g_dx[(size_t)n0 * 3 + 2], part0 * sDirz[r0]);
        atomicAdd(&g_dx[(size_t)n1 * 3 + 0], part1 * sDirx[r0 + 8]);
        atomicAdd(&g_dx[(size_t)n1 * 3 + 1], part1 * sDiry[r0 + 8]);
        atomicAdd(&g_dx[(size_t)n1 * 3 + 2], part1 * sDirz[r0 + 8]);
    }
    __syncthreads();

    // scatter m2 -> g_dh with vector reductions (2 threads per edge)
    {
        const int e    = tid & 127;
        const int half = tid >> 7;
        const int node = sSrc[e];
        float* dst = g_dh + (size_t)node * 64 + half * 32;
        const float* src = sOut + e * 72 + half * 32;
#pragma unroll
        for (int i = 0; i < 8; i++) {
            const float4 v = *(const float4*)(src + i * 4);
            red_add_v4(dst + i * 4, v);
        }
    }
}

// ---------------- x_new = x + delta_x ----------------
__global__ void xout_kernel(const float* __restrict__ x, float* __restrict__ out) {
    const int i = blockIdx.x * blockDim.x + threadIdx.x;
    if (i < BN * 3) out[i] = x[i] + g_dx[i];
}

// ---------------- launch ----------------
extern "C" void kernel_launch(void* const* d_in, const int* in_sizes, int n_in,
                              void* d_out, int out_size) {
    const float* x   = (const float*)d_in[0];
    const float* h   = (const float*)d_in[1];
    const int*   ei  = (const int*)d_in[2];
    const float* pw1 = (const float*)d_in[3];
    const float* pb1 = (const float*)d_in[4];
    const float* pw2 = (const float*)d_in[5];
    const float* pb2 = (const float*)d_in[6];
    const float* pxw = (const float*)d_in[7];
    const float* hw1 = (const float*)d_in[8];
    const float* hb1 = (const float*)d_in[9];
    const float* hw2 = (const float*)d_in[10];
    const float* hb2 = (const float*)d_in[11];

    float* out   = (float*)d_out;
    float* out_x = out;                      // (B,N,3) first
    float* out_h = out + (size_t)BN * 3;     // then (B,N,128)

    const int GSMEM = 2 * 10240 * (int)sizeof(float);                 // 81920 B
    const int EDGE_SMEM = (64 * 72 + 128 * 72) * (int)sizeof(float);  // 55296 B
    cudaFuncSetAttribute(gemm_tc<0, 128, 0>,  cudaFuncAttributeMaxDynamicSharedMemorySize, GSMEM);
    cudaFuncSetAttribute(gemm_tc<1, 192, 4>,  cudaFuncAttributeMaxDynamicSharedMemorySize, GSMEM);
    cudaFuncSetAttribute(gemm_tc<2, 128, 10>, cudaFuncAttributeMaxDynamicSharedMemorySize, GSMEM);
    cudaFuncSetAttribute(edge_kernel, cudaFuncAttributeMaxDynamicSharedMemorySize, EDGE_SMEM);

    prep_kernel<<<160, 256>>>(pw1, hw1, hw2, pw2);
    zero_kernel<<<1024, 256>>>();
    gemm_tc<0, 128, 0><<<BN / 128, 256, GSMEM>>>(h, nullptr, nullptr);   // g_P
    edge_kernel<<<NE / 128, 256, EDGE_SMEM>>>(x, ei, pw1, pb1, pb2, pxw); // g_dh, g_dx
    gemm_tc<1, 192, 4><<<BN / 128, 256, GSMEM>>>(h, hb1, nullptr);       // g_t
    gemm_tc<2, 128, 10><<<BN / 128, 256, GSMEM>>>(h, hb2, out_h);        // h_new
    xout_kernel<<<(BN * 3 + 255) / 256, 256>>>(x, out_x);                // x_new
}

// round 5
// speedup vs baseline: 1.2930x; 1.2803x over previous
#include <cuda_runtime.h>
#include <math.h>
#include <stdint.h>

#define BN   65536      // B*N total nodes
#define NPB  16384      // nodes per batch
#define NE   262144     // total edges (B*E)
#define EPB  256        // edges per block (edge kernel)

// ---------------- device scratch ----------------
__device__ __align__(16) float g_P [(size_t)BN * 128];   // [P1 | P2] per node
__device__ __align__(16) float g_dh[(size_t)BN * 64];    // scattered m_ij
__device__ __align__(16) float g_dx[(size_t)BN * 3];     // scattered delta_x
__device__ __align__(16) float g_t [(size_t)BN * 128];   // silu(h_input @ ph_w1 + b1)
// Prepped weights: 14 K-chunks x 128 n-rows x 40 words (tf32, k-pair interleaved)
__device__ __align__(16) float g_Bp[14 * 128 * 40];
__device__ __align__(16) float g_W2p[64 * 72];            // pe_w2, [n][72] interleaved

__device__ __forceinline__ float silu_f(float v) {
    return v * (1.0f / (1.0f + __expf(-v)));
}

__device__ __forceinline__ uint32_t f2tf32(float f) {
    uint32_t r;
    asm("cvt.rna.tf32.f32 %0, %1;" : "=r"(r) : "f"(f));
    return r;
}

__device__ __forceinline__ void mma_tf32(float* c, const uint32_t* a, const uint32_t* b) {
    asm volatile("mma.sync.aligned.m16n8k8.row.col.f32.tf32.tf32.f32 "
        "{%0,%1,%2,%3}, {%4,%5,%6,%7}, {%8,%9}, {%0,%1,%2,%3};"
        : "+f"(c[0]), "+f"(c[1]), "+f"(c[2]), "+f"(c[3])
        : "r"(a[0]), "r"(a[1]), "r"(a[2]), "r"(a[3]), "r"(b[0]), "r"(b[1]));
}

__device__ __forceinline__ void red_add_v2(float* p, float a, float b) {
    asm volatile("red.global.add.v2.f32 [%0], {%1,%2};"
                 :: "l"(p), "f"(a), "f"(b) : "memory");
}

__device__ __forceinline__ void cp_async16(uint32_t dst, const void* src) {
    asm volatile("cp.async.cg.shared.global [%0], [%1], 16;" :: "r"(dst), "l"(src));
}

// ---------------- weight prep: reshuffle + tf32-convert once ----------------
__global__ void prep_kernel(const float* __restrict__ pw1,
                            const float* __restrict__ hw1,
                            const float* __restrict__ hw2,
                            const float* __restrict__ pw2)
{
    const int stride = gridDim.x * blockDim.x;
    const int idx0 = blockIdx.x * blockDim.x + threadIdx.x;
    for (int i = idx0; i < 14 * 128 * 40; i += stride) {
        const int w = i % 40, n = (i / 40) & 127, c = i / (40 * 128);
        float v = 0.f;
        if (w < 32) {
            const int g = w >> 3, s = w & 7;
            const int k8 = (s >> 1) + ((s & 1) << 2);
            if (c < 4) {                 // pe_w1 split [W1a|W1b]
                const int k = c * 32 + g * 8 + k8;
                v = (n < 64) ? pw1[k * 64 + n] : pw1[(128 + k) * 64 + (n - 64)];
            } else if (c < 10) {         // ph_w1, K=192
                const int k = (c - 4) * 32 + g * 8 + k8;
                v = hw1[k * 128 + n];
            } else {                     // ph_w2, K=128
                const int k = (c - 10) * 32 + g * 8 + k8;
                v = hw2[k * 128 + n];
            }
            v = __uint_as_float(f2tf32(v));
        }
        g_Bp[i] = v;
    }
    for (int i = idx0; i < 64 * 72; i += stride) {
        const int w = i % 72, n = i / 72;
        float v = 0.f;
        if (w < 64) {
            const int g = w >> 3, s = w & 7;
            const int k = g * 8 + (s >> 1) + ((s & 1) << 2);
            v = __uint_as_float(f2tf32(pw2[k * 64 + n]));
        }
        g_W2p[i] = v;
    }
}

// ---------------- zero the scatter accumulators ----------------
__global__ void zero_kernel() {
    float4 z = make_float4(0.f, 0.f, 0.f, 0.f);
    const size_t n1 = (size_t)BN * 16;
    const size_t n2 = (size_t)BN * 3 / 4;
    const size_t total = n1 + n2;
    for (size_t i = (size_t)blockIdx.x * blockDim.x + threadIdx.x; i < total;
         i += (size_t)gridDim.x * blockDim.x) {
        if (i < n1) ((float4*)g_dh)[i] = z;
        else        ((float4*)g_dx)[i - n1] = z;
    }
}

// ============ tf32 TC GEMM: CTA 128x128, warp 32x64, double-buffered ========
template<int MODE, int KTOT, int BOFF>
__global__ __launch_bounds__(256, 2) void gemm_tc(
    const float* __restrict__ A,
    const float* __restrict__ bias,
    float* __restrict__ Cout)
{
    extern __shared__ float sm[];
    const int BUFW = 10240;

    const int tid  = threadIdx.x;
    const int lane = tid & 31, warp = tid >> 5;
    const int wm = warp & 3, wn = warp >> 2;
    const int gq = lane >> 2, tq = lane & 3;
    const int m0 = blockIdx.x * 128;
    const int NC = KTOT / 32;

    const uint32_t smem_u32 = (uint32_t)__cvta_generic_to_shared(sm);

    float acc[2][8][4];
#pragma unroll
    for (int i = 0; i < 2; i++)
#pragma unroll
        for (int j = 0; j < 8; j++)
#pragma unroll
            for (int q = 0; q < 4; q++) acc[i][j][q] = 0.f;

    float4 ra[4];
    const int am = tid >> 1;
    const int ah = (tid & 1) * 16;

    auto ldgA = [&](int k0) {
        const int f = k0 + ah;
        const float* src;
        if (MODE == 1) {
            src = (f < 128) ? (A + (size_t)(m0 + am) * 128 + f)
                            : (g_dh + (size_t)(m0 + am) * 64 + (f - 128));
        } else if (MODE == 2) {
            src = g_t + (size_t)(m0 + am) * 128 + f;
        } else {
            src = A + (size_t)(m0 + am) * 128 + f;
        }
        ra[0] = *(const float4*)(src);
        ra[1] = *(const float4*)(src + 4);
        ra[2] = *(const float4*)(src + 8);
        ra[3] = *(const float4*)(src + 12);
    };

    auto stsA = [&](int p) {
        float* bA = sm + p * BUFW;
#pragma unroll
        for (int pg = 0; pg < 2; pg++) {
            const float4 u = ra[pg * 2], v = ra[pg * 2 + 1];
            uint4 w0, w1;
            w0.x = f2tf32(u.x); w0.y = f2tf32(v.x); w0.z = f2tf32(u.y); w0.w = f2tf32(v.y);
            w1.x = f2tf32(u.z); w1.y = f2tf32(v.z); w1.z = f2tf32(u.w); w1.w = f2tf32(v.w);
            *(uint4*)&bA[am * 40 + ah + pg * 8]     = w0;
            *(uint4*)&bA[am * 40 + ah + pg * 8 + 4] = w1;
        }
    };

    auto cpB = [&](int c, int p) {
        const float* src = g_Bp + (size_t)(BOFF + c) * 5120;
        const uint32_t dst = smem_u32 + (p * BUFW + 5120) * 4;
#pragma unroll
        for (int it = 0; it < 5; it++) {
            const int q = tid + it * 256;
            cp_async16(dst + q * 16, src + q * 4);
        }
        asm volatile("cp.async.commit_group;" ::: "memory");
    };

    auto compute = [&](int p) {
        const uint32_t* bA = (const uint32_t*)(sm + p * BUFW);
        const uint32_t* bB = (const uint32_t*)(sm + p * BUFW + 5120);
#pragma unroll
        for (int ks = 0; ks < 4; ks++) {
            uint32_t af[2][4], bf[8][2];
#pragma unroll
            for (int i = 0; i < 2; i++) {
                const int r = wm * 32 + i * 16 + gq;
                const uint2 lo = *(const uint2*)&bA[r * 40 + ks * 8 + 2 * tq];
                const uint2 hi = *(const uint2*)&bA[(r + 8) * 40 + ks * 8 + 2 * tq];
                af[i][0] = lo.x; af[i][1] = hi.x; af[i][2] = lo.y; af[i][3] = hi.y;
            }
#pragma unroll
            for (int j = 0; j < 8; j++) {
                const int c = wn * 64 + j * 8 + gq;
                const uint2 b = *(const uint2*)&bB[c * 40 + ks * 8 + 2 * tq];
                bf[j][0] = b.x; bf[j][1] = b.y;
            }
#pragma unroll
            for (int i = 0; i < 2; i++)
#pragma unroll
                for (int j = 0; j < 8; j++)
                    mma_tf32(acc[i][j], af[i], bf[j]);
        }
    };

    ldgA(0);
    cpB(0, 0);
    stsA(0);
    asm volatile("cp.async.wait_group 0;" ::: "memory");
    __syncthreads();
    for (int c = 0; c < NC; c++) {
        if (c + 1 < NC) { ldgA((c + 1) * 32); cpB(c + 1, (c + 1) & 1); }
        compute(c & 1);
        if (c + 1 < NC) stsA((c + 1) & 1);
        asm volatile("cp.async.wait_group 0;" ::: "memory");
        __syncthreads();
    }

    // ---- epilogue ----
#pragma unroll
    for (int i = 0; i < 2; i++) {
#pragma unroll
        for (int h2 = 0; h2 < 2; h2++) {
            const int r = m0 + wm * 32 + i * 16 + gq + h2 * 8;
#pragma unroll
            for (int j = 0; j < 8; j++) {
                const int c = wn * 64 + j * 8 + tq * 2;
                float v0 = acc[i][j][h2 * 2 + 0];
                float v1 = acc[i][j][h2 * 2 + 1];
                const size_t base = (size_t)r * 128 + c;
                if (MODE == 0) {
                    *(float2*)(g_P + base) = make_float2(v0, v1);
                } else if (MODE == 1) {
                    v0 = silu_f(v0 + __ldg(bias + c));
                    v1 = silu_f(v1 + __ldg(bias + c + 1));
                    *(float2*)(g_t + base) = make_float2(v0, v1);
                } else {
                    const float2 hh = *(const float2*)(A + base);
                    v0 += __ldg(bias + c) + hh.x;
                    v1 += __ldg(bias + c + 1) + hh.y;
                    *(float2*)(Cout + base) = make_float2(v0, v1);
                }
            }
        }
    }
}

// ---------------- edge kernel: 256 edges/block, 512 threads ----------------
__global__ __launch_bounds__(512, 2) void edge_kernel(
    const float* __restrict__ x,
    const int*   __restrict__ edges,
    const float* __restrict__ W1,
    const float* __restrict__ b1,
    const float* __restrict__ b2,
    const float* __restrict__ pxw)
{
    extern __shared__ float dyn[];
    float* sW2 = dyn;                    // [64][72] tf32, interleaved
    float* sM  = dyn + 64 * 72;          // [256][72] tf32, interleaved
    const uint32_t* sW2u = (const uint32_t*)sW2;
    const uint32_t* sMu  = (const uint32_t*)sM;

    __shared__ int   sSrc[EPB], sDst[EPB];
    __shared__ float sD2[EPB];
    __shared__ float sDirx[EPB], sDiry[EPB], sDirz[EPB];
    __shared__ float sB1[64], sB2[64], sPx[64], sW1r[64];

    const int tid  = threadIdx.x;
    const int lane = tid & 31, warp = tid >> 5;
    const int gq = lane >> 2, tq = lane & 3;
    const int e0 = blockIdx.x * EPB;

    if (tid < EPB) {
        const int eg = e0 + tid;
        const int b  = eg >> 16;                 // E per batch = 65536
        const int2 sd = ((const int2*)edges)[eg];
        const int gi = b * NPB + sd.x;
        const int gj = b * NPB + sd.y;
        sSrc[tid] = gi; sDst[tid] = gj;
        const float xi0 = x[(size_t)gi * 3 + 0], xi1 = x[(size_t)gi * 3 + 1], xi2 = x[(size_t)gi * 3 + 2];
        const float xj0 = x[(size_t)gj * 3 + 0], xj1 = x[(size_t)gj * 3 + 1], xj2 = x[(size_t)gj * 3 + 2];
        const float d0 = xi0 - xj0, d1 = xi1 - xj1, d2c = xi2 - xj2;
        float d2 = d0 * d0 + d1 * d1 + d2c * d2c;
        d2 = fmaxf(d2, 1e-12f);
        sD2[tid] = d2;
        const float inv = 1.0f / (sqrtf(d2) + 1e-8f);
        sDirx[tid] = d0 * inv; sDiry[tid] = d1 * inv; sDirz[tid] = d2c * inv;
    }
    if (tid < 64) {
        sB1[tid] = b1[tid];
        sB2[tid] = b2[tid];
        sPx[tid] = pxw[tid];
        sW1r[tid] = W1[256 * 64 + tid];
    }
    // W2 prepped: straight copy 64*72 words = 1152 uint4
#pragma unroll
    for (int it = 0; it < 3; it++) {
        const int q = tid + it * 512;
        if (q < 1152) *(float4*)&sW2[q * 4] = *(const float4*)&g_W2p[q * 4];
    }
    __syncthreads();

    // m tile: silu(P1[src] + P2[dst] + dist2*W1r + b1) -> interleaved tf32
    // float4 gathers: item = (edge e, quad q of 16); k = 4q + j
#pragma unroll
    for (int it = 0; it < 8; ++it) {
        const int idx = it * 512 + tid;
        const int e = idx >> 4, q = idx & 15;
        const float4 a = *(const float4*)(g_P + (size_t)sSrc[e] * 128 + q * 4);
        const float4 b = *(const float4*)(g_P + (size_t)sDst[e] * 128 + 64 + q * 4);
        const float4 wv = *(const float4*)&sW1r[q * 4];
        const float4 bv = *(const float4*)&sB1[q * 4];
        const float d2 = sD2[e];
        float* dst = &sM[e * 72 + (q >> 1) * 8 + (q & 1)];
        dst[0] = __uint_as_float(f2tf32(silu_f(a.x + b.x + d2 * wv.x + bv.x)));
        dst[2] = __uint_as_float(f2tf32(silu_f(a.y + b.y + d2 * wv.y + bv.y)));
        dst[4] = __uint_as_float(f2tf32(silu_f(a.z + b.z + d2 * wv.z + bv.z)));
        dst[6] = __uint_as_float(f2tf32(silu_f(a.w + b.w + d2 * wv.w + bv.w)));
    }
    __syncthreads();

    // GEMM2 via tf32 mma: each warp 16 edges x 64 cols, K=64
    float acc[8][4];
#pragma unroll
    for (int j = 0; j < 8; j++)
#pragma unroll
        for (int q = 0; q < 4; q++) acc[j][q] = 0.f;

#pragma unroll
    for (int ks = 0; ks < 8; ks++) {
        uint32_t af[4], bf[2];
        const int r = warp * 16 + gq;
        const uint2 lo = *(const uint2*)&sMu[r * 72 + ks * 8 + 2 * tq];
        const uint2 hi = *(const uint2*)&sMu[(r + 8) * 72 + ks * 8 + 2 * tq];
        af[0] = lo.x; af[1] = hi.x; af[2] = lo.y; af[3] = hi.y;
#pragma unroll
        for (int j = 0; j < 8; j++) {
            const int c = j * 8 + gq;
            const uint2 b = *(const uint2*)&sW2u[c * 72 + ks * 8 + 2 * tq];
            bf[0] = b.x; bf[1] = b.y;
            mma_tf32(acc[j], af, bf);
        }
    }

    // epilogue: silu(+b2), reduce straight from registers
    const int r0 = warp * 16 + gq;
    const int n0 = sSrc[r0], n1 = sSrc[r0 + 8];
    float part0 = 0.f, part1 = 0.f;
#pragma unroll
    for (int j = 0; j < 8; j++) {
        const int c = j * 8 + tq * 2;
        const float bb0 = sB2[c], bb1 = sB2[c + 1];
        const float px0 = sPx[c], px1 = sPx[c + 1];
        const float v0 = silu_f(acc[j][0] + bb0);
        const float v1 = silu_f(acc[j][1] + bb1);
        const float v2 = silu_f(acc[j][2] + bb0);
        const float v3 = silu_f(acc[j][3] + bb1);
        part0 += v0 * px0 + v1 * px1;
        part1 += v2 * px0 + v3 * px1;
        red_add_v2(g_dh + (size_t)n0 * 64 + c, v0, v1);
        red_add_v2(g_dh + (size_t)n1 * 64 + c, v2, v3);
    }
    part0 += __shfl_xor_sync(0xffffffffu, part0, 1);
    part0 += __shfl_xor_sync(0xffffffffu, part0, 2);
    part1 += __shfl_xor_sync(0xffffffffu, part1, 1);
    part1 += __shfl_xor_sync(0xffffffffu, part1, 2);
    if (tq == 0) {
        atomicAdd(&g_dx[(size_t)n0 * 3 + 0], part0 * sDirx[r0]);
        atomicAdd(&g_dx[(size_t)n0 * 3 + 1], part0 * sDiry[r0]);
        atomicAdd(&g_dx[(size_t)n0 * 3 + 2], part0 * sDirz[r0]);
        atomicAdd(&g_dx[(size_t)n1 * 3 + 0], part1 * sDirx[r0 + 8]);
        atomicAdd(&g_dx[(size_t)n1 * 3 + 1], part1 * sDiry[r0 + 8]);
        atomicAdd(&g_dx[(size_t)n1 * 3 + 2], part1 * sDirz[r0 + 8]);
    }
}

// ---------------- x_new = x + delta_x ----------------
__global__ void xout_kernel(const float* __restrict__ x, float* __restrict__ out) {
    const int i = blockIdx.x * blockDim.x + threadIdx.x;
    if (i < BN * 3) out[i] = x[i] + g_dx[i];
}

// ---------------- launch ----------------
extern "C" void kernel_launch(void* const* d_in, const int* in_sizes, int n_in,
                              void* d_out, int out_size) {
    const float* x   = (const float*)d_in[0];
    const float* h   = (const float*)d_in[1];
    const int*   ei  = (const int*)d_in[2];
    const float* pw1 = (const float*)d_in[3];
    const float* pb1 = (const float*)d_in[4];
    const float* pw2 = (const float*)d_in[5];
    const float* pb2 = (const float*)d_in[6];
    const float* pxw = (const float*)d_in[7];
    const float* hw1 = (const float*)d_in[8];
    const float* hb1 = (const float*)d_in[9];
    const float* hw2 = (const float*)d_in[10];
    const float* hb2 = (const float*)d_in[11];

    float* out   = (float*)d_out;
    float* out_x = out;                      // (B,N,3) first
    float* out_h = out + (size_t)BN * 3;     // then (B,N,128)

    const int GSMEM = 2 * 10240 * (int)sizeof(float);                  // 81920 B
    const int EDGE_SMEM = (64 * 72 + EPB * 72) * (int)sizeof(float);   // 92160 B
    cudaFuncSetAttribute(gemm_tc<0, 128, 0>,  cudaFuncAttributeMaxDynamicSharedMemorySize, GSMEM);
    cudaFuncSetAttribute(gemm_tc<1, 192, 4>,  cudaFuncAttributeMaxDynamicSharedMemorySize, GSMEM);
    cudaFuncSetAttribute(gemm_tc<2, 128, 10>, cudaFuncAttributeMaxDynamicSharedMemorySize, GSMEM);
    cudaFuncSetAttribute(edge_kernel, cudaFuncAttributeMaxDynamicSharedMemorySize, EDGE_SMEM);

    prep_kernel<<<160, 256>>>(pw1, hw1, hw2, pw2);
    zero_kernel<<<1024, 256>>>();
    gemm_tc<0, 128, 0><<<BN / 128, 256, GSMEM>>>(h, nullptr, nullptr);    // g_P
    edge_kernel<<<NE / EPB, 512, EDGE_SMEM>>>(x, ei, pw1, pb1, pb2, pxw); // g_dh, g_dx
    gemm_tc<1, 192, 4><<<BN / 128, 256, GSMEM>>>(h, hb1, nullptr);        // g_t
    gemm_tc<2, 128, 10><<<BN / 128, 256, GSMEM>>>(h, hb2, out_h);         // h_new
    xout_kernel<<<(BN * 3 + 255) / 256, 256>>>(x, out_x);                 // x_new
}

// round 6
// speedup vs baseline: 1.3110x; 1.0139x over previous
#include <cuda_runtime.h>
#include <math.h>
#include <stdint.h>

#define BN   65536      // B*N total nodes
#define NPB  16384      // nodes per batch
#define NE   262144     // total edges (B*E)
#define EPB  128        // edges per block (edge kernel)

// ---------------- device scratch ----------------
__device__ __align__(16) float g_P [(size_t)BN * 128];   // [P1 | P2] per node
__device__ __align__(16) float g_dh[(size_t)BN * 64];    // scattered m_ij
__device__ __align__(16) float g_dx[(size_t)BN * 3];     // scattered delta_x
__device__ __align__(16) float g_t [(size_t)BN * 128];   // silu(h_input @ ph_w1 + b1)
// Prepped weights: 14 K-chunks x 128 n-rows x 40 words (tf32, k-pair interleaved)
__device__ __align__(16) float g_Bp[14 * 128 * 40];
__device__ __align__(16) float g_W2p[64 * 72];            // pe_w2, [n][72] interleaved

__device__ __forceinline__ float silu_f(float v) {
    return v * (1.0f / (1.0f + __expf(-v)));
}

__device__ __forceinline__ uint32_t f2tf32(float f) {
    uint32_t r;
    asm("cvt.rna.tf32.f32 %0, %1;" : "=r"(r) : "f"(f));
    return r;
}

__device__ __forceinline__ void mma_tf32(float* c, const uint32_t* a, const uint32_t* b) {
    asm volatile("mma.sync.aligned.m16n8k8.row.col.f32.tf32.tf32.f32 "
        "{%0,%1,%2,%3}, {%4,%5,%6,%7}, {%8,%9}, {%0,%1,%2,%3};"
        : "+f"(c[0]), "+f"(c[1]), "+f"(c[2]), "+f"(c[3])
        : "r"(a[0]), "r"(a[1]), "r"(a[2]), "r"(a[3]), "r"(b[0]), "r"(b[1]));
}

__device__ __forceinline__ void red_add_v2(float* p, float a, float b) {
    asm volatile("red.global.add.v2.f32 [%0], {%1,%2};"
                 :: "l"(p), "f"(a), "f"(b) : "memory");
}

__device__ __forceinline__ void cp_async16(uint32_t dst, const void* src) {
    asm volatile("cp.async.cg.shared.global [%0], [%1], 16;" :: "r"(dst), "l"(src));
}

// ------------- prep (weight reshuffle+cvt) fused with accumulator zeroing ---
__global__ void prep_kernel(const float* __restrict__ pw1,
                            const float* __restrict__ hw1,
                            const float* __restrict__ hw2,
                            const float* __restrict__ pw2)
{
    const int stride = gridDim.x * blockDim.x;
    const int idx0 = blockIdx.x * blockDim.x + threadIdx.x;

    // zero g_dh / g_dx (float4 granularity)
    {
        float4 z = make_float4(0.f, 0.f, 0.f, 0.f);
        const size_t n1 = (size_t)BN * 16;
        const size_t n2 = (size_t)BN * 3 / 4;
        const size_t total = n1 + n2;
        for (size_t i = idx0; i < total; i += stride) {
            if (i < n1) ((float4*)g_dh)[i] = z;
            else        ((float4*)g_dx)[i - n1] = z;
        }
    }
    // g_Bp
    for (int i = idx0; i < 14 * 128 * 40; i += stride) {
        const int w = i % 40, n = (i / 40) & 127, c = i / (40 * 128);
        float v = 0.f;
        if (w < 32) {
            const int g = w >> 3, s = w & 7;
            const int k8 = (s >> 1) + ((s & 1) << 2);
            if (c < 4) {
                const int k = c * 32 + g * 8 + k8;
                v = (n < 64) ? pw1[k * 64 + n] : pw1[(128 + k) * 64 + (n - 64)];
            } else if (c < 10) {
                const int k = (c - 4) * 32 + g * 8 + k8;
                v = hw1[k * 128 + n];
            } else {
                const int k = (c - 10) * 32 + g * 8 + k8;
                v = hw2[k * 128 + n];
            }
            v = __uint_as_float(f2tf32(v));
        }
        g_Bp[i] = v;
    }
    // g_W2p
    for (int i = idx0; i < 64 * 72; i += stride) {
        const int w = i % 72, n = i / 72;
        float v = 0.f;
        if (w < 64) {
            const int g = w >> 3, s = w & 7;
            const int k = g * 8 + (s >> 1) + ((s & 1) << 2);
            v = __uint_as_float(f2tf32(pw2[k * 64 + n]));
        }
        g_W2p[i] = v;
    }
}

// ============ tf32 TC GEMM: CTA 128x128, warp 32x64, double-buffered ========
// MODE 2 additionally runs xout (x_new = x + g_dx) in tail blocks >= 512.
template<int MODE, int KTOT, int BOFF>
__global__ __launch_bounds__(256, 2) void gemm_tc(
    const float* __restrict__ A,
    const float* __restrict__ bias,
    float* __restrict__ Cout,
    const float* __restrict__ X,
    float* __restrict__ OutX)
{
    extern __shared__ float sm[];
    const int BUFW = 10240;

    if (MODE == 2 && blockIdx.x >= 512) {
        const int t0 = (blockIdx.x - 512) * 256 + threadIdx.x;
        for (int i = t0; i < BN * 3; i += 256 * 256)
            OutX[i] = X[i] + g_dx[i];
        return;
    }

    const int tid  = threadIdx.x;
    const int lane = tid & 31, warp = tid >> 5;
    const int wm = warp & 3, wn = warp >> 2;
    const int gq = lane >> 2, tq = lane & 3;
    const int m0 = blockIdx.x * 128;
    const int NC = KTOT / 32;

    const uint32_t smem_u32 = (uint32_t)__cvta_generic_to_shared(sm);

    float acc[2][8][4];
#pragma unroll
    for (int i = 0; i < 2; i++)
#pragma unroll
        for (int j = 0; j < 8; j++)
#pragma unroll
            for (int q = 0; q < 4; q++) acc[i][j][q] = 0.f;

    float4 ra[4];
    const int am = tid >> 1;
    const int ah = (tid & 1) * 16;

    auto ldgA = [&](int k0) {
        const int f = k0 + ah;
        const float* src;
        if (MODE == 1) {
            src = (f < 128) ? (A + (size_t)(m0 + am) * 128 + f)
                            : (g_dh + (size_t)(m0 + am) * 64 + (f - 128));
        } else if (MODE == 2) {
            src = g_t + (size_t)(m0 + am) * 128 + f;
        } else {
            src = A + (size_t)(m0 + am) * 128 + f;
        }
        ra[0] = *(const float4*)(src);
        ra[1] = *(const float4*)(src + 4);
        ra[2] = *(const float4*)(src + 8);
        ra[3] = *(const float4*)(src + 12);
    };

    auto stsA = [&](int p) {
        float* bA = sm + p * BUFW;
#pragma unroll
        for (int pg = 0; pg < 2; pg++) {
            const float4 u = ra[pg * 2], v = ra[pg * 2 + 1];
            uint4 w0, w1;
            w0.x = f2tf32(u.x); w0.y = f2tf32(v.x); w0.z = f2tf32(u.y); w0.w = f2tf32(v.y);
            w1.x = f2tf32(u.z); w1.y = f2tf32(v.z); w1.z = f2tf32(u.w); w1.w = f2tf32(v.w);
            *(uint4*)&bA[am * 40 + ah + pg * 8]     = w0;
            *(uint4*)&bA[am * 40 + ah + pg * 8 + 4] = w1;
        }
    };

    auto cpB = [&](int c, int p) {
        const float* src = g_Bp + (size_t)(BOFF + c) * 5120;
        const uint32_t dst = smem_u32 + (p * BUFW + 5120) * 4;
#pragma unroll
        for (int it = 0; it < 5; it++) {
            const int q = tid + it * 256;
            cp_async16(dst + q * 16, src + q * 4);
        }
        asm volatile("cp.async.commit_group;" ::: "memory");
    };

    auto compute = [&](int p) {
        const uint32_t* bA = (const uint32_t*)(sm + p * BUFW);
        const uint32_t* bB = (const uint32_t*)(sm + p * BUFW + 5120);
#pragma unroll
        for (int ks = 0; ks < 4; ks++) {
            uint32_t af[2][4], bf[8][2];
#pragma unroll
            for (int i = 0; i < 2; i++) {
                const int r = wm * 32 + i * 16 + gq;
                const uint2 lo = *(const uint2*)&bA[r * 40 + ks * 8 + 2 * tq];
                const uint2 hi = *(const uint2*)&bA[(r + 8) * 40 + ks * 8 + 2 * tq];
                af[i][0] = lo.x; af[i][1] = hi.x; af[i][2] = lo.y; af[i][3] = hi.y;
            }
#pragma unroll
            for (int j = 0; j < 8; j++) {
                const int c = wn * 64 + j * 8 + gq;
                const uint2 b = *(const uint2*)&bB[c * 40 + ks * 8 + 2 * tq];
                bf[j][0] = b.x; bf[j][1] = b.y;
            }
#pragma unroll
            for (int i = 0; i < 2; i++)
#pragma unroll
                for (int j = 0; j < 8; j++)
                    mma_tf32(acc[i][j], af[i], bf[j]);
        }
    };

    ldgA(0);
    cpB(0, 0);
    stsA(0);
    asm volatile("cp.async.wait_group 0;" ::: "memory");
    __syncthreads();
    for (int c = 0; c < NC; c++) {
        if (c + 1 < NC) { ldgA((c + 1) * 32); cpB(c + 1, (c + 1) & 1); }
        compute(c & 1);
        if (c + 1 < NC) stsA((c + 1) & 1);
        asm volatile("cp.async.wait_group 0;" ::: "memory");
        __syncthreads();
    }

    // ---- epilogue ----
#pragma unroll
    for (int i = 0; i < 2; i++) {
#pragma unroll
        for (int h2 = 0; h2 < 2; h2++) {
            const int r = m0 + wm * 32 + i * 16 + gq + h2 * 8;
#pragma unroll
            for (int j = 0; j < 8; j++) {
                const int c = wn * 64 + j * 8 + tq * 2;
                float v0 = acc[i][j][h2 * 2 + 0];
                float v1 = acc[i][j][h2 * 2 + 1];
                const size_t base = (size_t)r * 128 + c;
                if (MODE == 0) {
                    *(float2*)(g_P + base) = make_float2(v0, v1);
                } else if (MODE == 1) {
                    v0 = silu_f(v0 + __ldg(bias + c));
                    v1 = silu_f(v1 + __ldg(bias + c + 1));
                    *(float2*)(g_t + base) = make_float2(v0, v1);
                } else {
                    const float2 hh = *(const float2*)(A + base);
                    v0 += __ldg(bias + c) + hh.x;
                    v1 += __ldg(bias + c + 1) + hh.y;
                    *(float2*)(Cout + base) = make_float2(v0, v1);
                }
            }
        }
    }
}

// -------- edge kernel: 128 edges/block, 256 threads, 4 CTAs/SM, K-split -----
__global__ __launch_bounds__(256, 4) void edge_kernel(
    const float* __restrict__ x,
    const int*   __restrict__ edges,
    const float* __restrict__ W1,
    const float* __restrict__ b1,
    const float* __restrict__ b2,
    const float* __restrict__ pxw)
{
    extern __shared__ float dyn[];
    float* sW2 = dyn;                    // [64][72] tf32, interleaved (full K)
    float* sM  = dyn + 64 * 72;          // [128][36] tf32, interleaved (K half)
    const uint32_t* sW2u = (const uint32_t*)sW2;
    const uint32_t* sMu  = (const uint32_t*)sM;

    __shared__ int   sSrc[EPB], sDst[EPB];
    __shared__ float sD2[EPB];
    __shared__ float sDirx[EPB], sDiry[EPB], sDirz[EPB];
    __shared__ float sB1[64], sB2[64], sPx[64], sW1r[64];

    const int tid  = threadIdx.x;
    const int lane = tid & 31, warp = tid >> 5;
    const int gq = lane >> 2, tq = lane & 3;
    const int e0 = blockIdx.x * EPB;

    if (tid < EPB) {
        const int eg = e0 + tid;
        const int b  = eg >> 16;                 // E per batch = 65536
        const int2 sd = ((const int2*)edges)[eg];
        const int gi = b * NPB + sd.x;
        const int gj = b * NPB + sd.y;
        sSrc[tid] = gi; sDst[tid] = gj;
        const float xi0 = x[(size_t)gi * 3 + 0], xi1 = x[(size_t)gi * 3 + 1], xi2 = x[(size_t)gi * 3 + 2];
        const float xj0 = x[(size_t)gj * 3 + 0], xj1 = x[(size_t)gj * 3 + 1], xj2 = x[(size_t)gj * 3 + 2];
        const float d0 = xi0 - xj0, d1 = xi1 - xj1, d2c = xi2 - xj2;
        float d2 = d0 * d0 + d1 * d1 + d2c * d2c;
        d2 = fmaxf(d2, 1e-12f);
        sD2[tid] = d2;
        const float inv = 1.0f / (sqrtf(d2) + 1e-8f);
        sDirx[tid] = d0 * inv; sDiry[tid] = d1 * inv; sDirz[tid] = d2c * inv;
    }
    if (tid >= 128 && tid < 192) {
        const int t = tid - 128;
        sB1[t] = b1[t];
        sB2[t] = b2[t];
        sPx[t] = pxw[t];
        sW1r[t] = W1[256 * 64 + t];
    }
    // W2 prepped: copy 64*72 words = 1152 uint4
#pragma unroll
    for (int it = 0; it < 5; it++) {
        const int q = tid + it * 256;
        if (q < 1152) *(float4*)&sW2[q * 4] = *(const float4*)&g_W2p[q * 4];
    }
    __syncthreads();

    float acc[8][4];
#pragma unroll
    for (int j = 0; j < 8; j++)
#pragma unroll
        for (int q = 0; q < 4; q++) acc[j][q] = 0.f;

#pragma unroll
    for (int h = 0; h < 2; h++) {
        // gather half: k in [32h, 32h+32)
#pragma unroll
        for (int it = 0; it < 4; ++it) {
            const int idx = it * 256 + tid;
            const int e = idx >> 3, qp = idx & 7;   // qp: quad within half
            const int k = h * 32 + qp * 4;
            const float4 a = *(const float4*)(g_P + (size_t)sSrc[e] * 128 + k);
            const float4 b = *(const float4*)(g_P + (size_t)sDst[e] * 128 + 64 + k);
            const float4 wv = *(const float4*)&sW1r[k];
            const float4 bv = *(const float4*)&sB1[k];
            const float d2 = sD2[e];
            float* dst = &sM[e * 36 + (qp >> 1) * 8 + (qp & 1)];
            dst[0] = __uint_as_float(f2tf32(silu_f(a.x + b.x + d2 * wv.x + bv.x)));
            dst[2] = __uint_as_float(f2tf32(silu_f(a.y + b.y + d2 * wv.y + bv.y)));
            dst[4] = __uint_as_float(f2tf32(silu_f(a.z + b.z + d2 * wv.z + bv.z)));
            dst[6] = __uint_as_float(f2tf32(silu_f(a.w + b.w + d2 * wv.w + bv.w)));
        }
        __syncthreads();

        // mma over this half's 4 k-groups
#pragma unroll
        for (int ksl = 0; ksl < 4; ksl++) {
            const int ks = h * 4 + ksl;
            uint32_t af[4], bf[2];
            const int r = warp * 16 + gq;
            const uint2 lo = *(const uint2*)&sMu[r * 36 + ksl * 8 + 2 * tq];
            const uint2 hi = *(const uint2*)&sMu[(r + 8) * 36 + ksl * 8 + 2 * tq];
            af[0] = lo.x; af[1] = hi.x; af[2] = lo.y; af[3] = hi.y;
#pragma unroll
            for (int j = 0; j < 8; j++) {
                const int c = j * 8 + gq;
                const uint2 b = *(const uint2*)&sW2u[c * 72 + ks * 8 + 2 * tq];
                bf[0] = b.x; bf[1] = b.y;
                mma_tf32(acc[j], af, bf);
            }
        }
        if (h == 0) __syncthreads();   // protect sM before overwrite
    }

    // epilogue: silu(+b2), reduce straight from registers
    const int r0 = warp * 16 + gq;
    const int n0 = sSrc[r0], n1 = sSrc[r0 + 8];
    float part0 = 0.f, part1 = 0.f;
#pragma unroll
    for (int j = 0; j < 8; j++) {
        const int c = j * 8 + tq * 2;
        const float bb0 = sB2[c], bb1 = sB2[c + 1];
        const float px0 = sPx[c], px1 = sPx[c + 1];
        const float v0 = silu_f(acc[j][0] + bb0);
        const float v1 = silu_f(acc[j][1] + bb1);
        const float v2 = silu_f(acc[j][2] + bb0);
        const float v3 = silu_f(acc[j][3] + bb1);
        part0 += v0 * px0 + v1 * px1;
        part1 += v2 * px0 + v3 * px1;
        red_add_v2(g_dh + (size_t)n0 * 64 + c, v0, v1);
        red_add_v2(g_dh + (size_t)n1 * 64 + c, v2, v3);
    }
    part0 += __shfl_xor_sync(0xffffffffu, part0, 1);
    part0 += __shfl_xor_sync(0xffffffffu, part0, 2);
    part1 += __shfl_xor_sync(0xffffffffu, part1, 1);
    part1 += __shfl_xor_sync(0xffffffffu, part1, 2);
    if (tq == 0) {
        atomicAdd(&g_dx[(size_t)n0 * 3 + 0], part0 * sDirx[r0]);
        atomicAdd(&g_dx[(size_t)n0 * 3 + 1], part0 * sDiry[r0]);
        atomicAdd(&g_dx[(size_t)n0 * 3 + 2], part0 * sDirz[r0]);
        atomicAdd(&g_dx[(size_t)n1 * 3 + 0], part1 * sDirx[r0 + 8]);
        atomicAdd(&g_dx[(size_t)n1 * 3 + 1], part1 * sDiry[r0 + 8]);
        atomicAdd(&g_dx[(size_t)n1 * 3 + 2], part1 * sDirz[r0 + 8]);
    }
}

// ---------------- launch ----------------
extern "C" void kernel_launch(void* const* d_in, const int* in_sizes, int n_in,
                              void* d_out, int out_size) {
    const float* x   = (const float*)d_in[0];
    const float* h   = (const float*)d_in[1];
    const int*   ei  = (const int*)d_in[2];
    const float* pw1 = (const float*)d_in[3];
    const float* pb1 = (const float*)d_in[4];
    const float* pw2 = (const float*)d_in[5];
    const float* pb2 = (const float*)d_in[6];
    const float* pxw = (const float*)d_in[7];
    const float* hw1 = (const float*)d_in[8];
    const float* hb1 = (const float*)d_in[9];
    const float* hw2 = (const float*)d_in[10];
    const float* hb2 = (const float*)d_in[11];

    float* out   = (float*)d_out;
    float* out_x = out;                      // (B,N,3) first
    float* out_h = out + (size_t)BN * 3;     // then (B,N,128)

    const int GSMEM = 2 * 10240 * (int)sizeof(float);                 // 81920 B
    const int EDGE_SMEM = (64 * 72 + EPB * 36) * (int)sizeof(float);  // 36864 B
    cudaFuncSetAttribute(gemm_tc<0, 128, 0>,  cudaFuncAttributeMaxDynamicSharedMemorySize, GSMEM);
    cudaFuncSetAttribute(gemm_tc<1, 192, 4>,  cudaFuncAttributeMaxDynamicSharedMemorySize, GSMEM);
    cudaFuncSetAttribute(gemm_tc<2, 128, 10>, cudaFuncAttributeMaxDynamicSharedMemorySize, GSMEM);
    cudaFuncSetAttribute(edge_kernel, cudaFuncAttributeMaxDynamicSharedMemorySize, EDGE_SMEM);

    prep_kernel<<<256, 256>>>(pw1, hw1, hw2, pw2);                        // weights + zero
    gemm_tc<0, 128, 0><<<BN / 128, 256, GSMEM>>>(h, nullptr, nullptr, nullptr, nullptr);
    edge_kernel<<<NE / EPB, 256, EDGE_SMEM>>>(x, ei, pw1, pb1, pb2, pxw); // g_dh, g_dx
    gemm_tc<1, 192, 4><<<BN / 128, 256, GSMEM>>>(h, hb1, nullptr, nullptr, nullptr);
    gemm_tc<2, 128, 10><<<BN / 128 + 256, 256, GSMEM>>>(h, hb2, out_h, x, out_x); // h_new + x_new
}